// round 16
// baseline (speedup 1.0000x reference)
#include <cuda_runtime.h>
#include <cuda_bf16.h>
#include <cuda_fp16.h>
#include <cstdint>

#define N_NODES 50000
#define N_EDGES 800000
#define DIM 128
#define NEG_SLOPE 0.01f

#define SCAN_BLK 1024
#define N_SCAN_BLKS ((N_NODES + SCAN_BLK - 1) / SCAN_BLK)   // 49
#define GEMV_BLKS  ((N_NODES + 255) / 256)                   // 196

// ---------------- scratch (static device globals; zero-init at load) --------
__device__ __half             g_zh[(size_t)N_NODES * DIM];  // z = h @ W (fp16)
__device__ float              g_ssrc[N_NODES];              // h . (W a_src)
__device__ unsigned long long g_sdoff[N_NODES];             // {offs(hi) | sdst bits(lo)}
__device__ int                g_count[N_NODES];             // in-degree histogram
__device__ int                g_offs[N_NODES + 1];          // CSR offsets (gather)
__device__ unsigned long long g_agg[N_SCAN_BLKS];           // scan aggregates
__device__ unsigned           g_bar1, g_bar2;               // monotone device barriers
__device__ unsigned           g_gemvdone;                   // gemv completion counter
__device__ unsigned long long g_pack[N_EDGES];              // {exp(e), src} by dst

// ======================= mma.sync helpers (plain sm_103 OK) ==================
__device__ __forceinline__ uint32_t smem_to_u32(const void* p) {
    uint32_t a;
    asm("{ .reg .u64 t; cvta.to.shared.u64 t, %1; cvt.u32.u64 %0, t; }"
        : "=r"(a) : "l"(p));
    return a;
}
#define LDSM4(r, addr) \
    asm volatile("ldmatrix.sync.aligned.m8n8.x4.shared.b16 {%0,%1,%2,%3}, [%4];" \
        : "=r"((r)[0]), "=r"((r)[1]), "=r"((r)[2]), "=r"((r)[3]) : "r"(addr))
#define LDSM2(r, addr) \
    asm volatile("ldmatrix.sync.aligned.m8n8.x2.shared.b16 {%0,%1}, [%2];" \
        : "=r"((r)[0]), "=r"((r)[1]) : "r"(addr))
#define MMA_BF16(c, a, b) \
    asm volatile("mma.sync.aligned.m16n8k16.row.col.f32.bf16.bf16.f32 " \
        "{%0,%1,%2,%3}, {%4,%5,%6,%7}, {%8,%9}, {%0,%1,%2,%3};" \
        : "+f"((c)[0]), "+f"((c)[1]), "+f"((c)[2]), "+f"((c)[3]) \
        : "r"((a)[0]), "r"((a)[1]), "r"((a)[2]), "r"((a)[3]), "r"((b)[0]), "r"((b)[1]))

#define STRA 72    // bf16 elems per smem row (64 data + 8 pad) -> conflict-free
#define KC   64    // K-chunk

// dynamic smem layout (bytes) for GEMM
#define SM_A_HI  0
#define SM_A_LO  (SM_A_HI + 128 * STRA * 2)
#define SM_B_HI  (SM_A_LO + 128 * STRA * 2)
#define SM_B_LO  (SM_B_HI + 128 * STRA * 2)
#define SM_TOTAL (SM_B_LO + 128 * STRA * 2)   // 73728 -> 2 CTAs/SM

__device__ __forceinline__ void split_bf16(float x, __nv_bfloat16& hi, __nv_bfloat16& lo) {
    hi = __float2bfloat16(x);
    lo = __float2bfloat16(x - __bfloat162float(hi));
}

// ---------------- gemv (fused): per-block wa = W@a, then 256 rows -------------
// ssrc[i] = h[i].(W@a_src); sdst -> sdoff.lo. Exact fp32 reorder of (h@W)@a.
// Signals completion via monotone counter (consumed by histscan phase C).
__global__ __launch_bounds__(256) void gemv_kernel(
        const float* __restrict__ h, const float* __restrict__ W,
        const float* __restrict__ a_src, const float* __restrict__ a_dst) {
    __shared__ float ws_s[DIM], wd_s[DIM];
    const int tid = threadIdx.x, warp = tid >> 5, lane = tid & 31;

    {
        float4 as = ((const float4*)a_src)[lane];
        float4 ad = ((const float4*)a_dst)[lane];
#pragma unroll
        for (int it = 0; it < 16; it++) {
            int k = warp + it * 8;
            float4 w = ((const float4*)W)[k * 32 + lane];
            float ps = w.x * as.x + w.y * as.y + w.z * as.z + w.w * as.w;
            float pd = w.x * ad.x + w.y * ad.y + w.z * ad.z + w.w * ad.w;
#pragma unroll
            for (int o = 16; o > 0; o >>= 1) {
                ps += __shfl_xor_sync(0xffffffffu, ps, o);
                pd += __shfl_xor_sync(0xffffffffu, pd, o);
            }
            if (lane == 0) { ws_s[k] = ps; wd_s[k] = pd; }
        }
    }
    __syncthreads();

    float4 ws = ((const float4*)ws_s)[lane];
    float4 wd = ((const float4*)wd_s)[lane];
    int rowBase = blockIdx.x * 256 + warp * 32;
#pragma unroll 4
    for (int i = 0; i < 32; i++) {
        int row = rowBase + i;
        if (row >= N_NODES) break;
        float4 v = ((const float4*)h)[(size_t)row * 32 + lane];
        float ps = v.x * ws.x + v.y * ws.y + v.z * ws.z + v.w * ws.w;
        float pd = v.x * wd.x + v.y * wd.y + v.z * wd.z + v.w * wd.w;
#pragma unroll
        for (int o = 16; o > 0; o >>= 1) {
            ps += __shfl_xor_sync(0xffffffffu, ps, o);
            pd += __shfl_xor_sync(0xffffffffu, pd, o);
        }
        if (lane == 0) {
            g_ssrc[row] = ps;
            ((unsigned*)&g_sdoff[row])[0] = __float_as_uint(pd);
        }
    }
    // publish completion (release: fence before increment)
    __threadfence();
    __syncthreads();
    if (tid == 0) atomicAdd(&g_gemvdone, 1u);
}

// monotone device barrier helper: returns the 1-based round number
__device__ __forceinline__ unsigned dev_barrier(unsigned* ctr, unsigned nblocks,
                                                unsigned* s_round) {
    __threadfence();
    __syncthreads();
    if (threadIdx.x == 0) {
        unsigned ret = atomicAdd(ctr, 1u);
        unsigned round = ret / nblocks + 1u;
        *s_round = round;
        volatile unsigned* p = ctr;
        while (*p < round * nblocks) { }
    }
    __syncthreads();
    return *s_round;
}

// ---------------- histscan + edgefill: one kernel, 3 phases -------------------
// A: histogram (dst/rank kept in registers). B: lookback scan. C: edgefill
// (waits on gemv's counter). 49 blocks, all wave-1 resident.
__global__ __launch_bounds__(SCAN_BLK) void histscan_kernel(
        const int* __restrict__ src, const int* __restrict__ dst) {
    const int tid = threadIdx.x, lane = tid & 31, warp = tid >> 5;
    const int bid = blockIdx.x;
    const int gthreads = N_SCAN_BLKS * SCAN_BLK;
    const int gtid = bid * SCAN_BLK + tid;
    __shared__ unsigned s_round1, s_round2;

    // ---- phase A: rank-returning histogram; dst/rank stay in registers
    int ds[16], rs[16];
#pragma unroll
    for (int it = 0; it < 4; it++) {
        int e0 = (gtid + it * gthreads) * 4;
        if (e0 + 3 < N_EDGES) {
            int4 d = *(const int4*)(dst + e0);
            ds[it * 4 + 0] = d.x; rs[it * 4 + 0] = atomicAdd(&g_count[d.x], 1);
            ds[it * 4 + 1] = d.y; rs[it * 4 + 1] = atomicAdd(&g_count[d.y], 1);
            ds[it * 4 + 2] = d.z; rs[it * 4 + 2] = atomicAdd(&g_count[d.z], 1);
            ds[it * 4 + 3] = d.w; rs[it * 4 + 3] = atomicAdd(&g_count[d.w], 1);
        } else {
#pragma unroll
            for (int k = 0; k < 4; k++) {
                int e = e0 + k;
                if (e < N_EDGES) {
                    int d = dst[e];
                    ds[it * 4 + k] = d;
                    rs[it * 4 + k] = atomicAdd(&g_count[d], 1);
                } else ds[it * 4 + k] = -1;
            }
        }
    }

    // ---- barrier 1
    dev_barrier(&g_bar1, N_SCAN_BLKS, &s_round1);

    // ---- phase B: exclusive scan with parallel lookback
    {
        __shared__ int wt[32];
        __shared__ int s_vals[64];
        __shared__ int s_base;
        const int i = bid * SCAN_BLK + tid;

        int v = 0;
        if (i < N_NODES) { v = g_count[i]; g_count[i] = 0; }   // read + self-clean
        int incl = v;
#pragma unroll
        for (int o = 1; o < 32; o <<= 1) {
            int t = __shfl_up_sync(0xffffffffu, incl, o);
            if (lane >= o) incl += t;
        }
        if (lane == 31) wt[warp] = incl;
        __syncthreads();
        if (warp == 0) {
            int x = wt[lane], ix = x;
#pragma unroll
            for (int o = 1; o < 32; o <<= 1) {
                int t = __shfl_up_sync(0xffffffffu, ix, o);
                if (lane >= o) ix += t;
            }
            wt[lane] = ix - x;
            if (lane == 31)
                atomicExch(&g_agg[bid], (1ull << 32) | (unsigned)ix);
        }
        __syncthreads();
        if (tid < bid) {
            volatile unsigned long long* p = (volatile unsigned long long*)&g_agg[tid];
            unsigned long long x;
            do { x = *p; } while (!(x >> 32));
            s_vals[tid] = (int)(unsigned)x;
        }
        __syncthreads();
        if (tid == 0) {
            int b = 0;
            for (int j = 0; j < bid; j++) b += s_vals[j];
            s_base = b;
            if (bid == N_SCAN_BLKS - 1) g_offs[N_NODES] = N_EDGES;
        }
        __syncthreads();
        if (i < N_NODES) {
            int off = s_base + wt[warp] + incl - v;
            g_offs[i] = off;
            ((int*)&g_sdoff[i])[1] = off;
        }
    }

    // ---- barrier 2 (offs must be globally visible before phase C)
    dev_barrier(&g_bar2, N_SCAN_BLKS, &s_round2);

    // reset scan aggregates for next replay (after everyone passed lookback)
    if (bid == 0 && tid < N_SCAN_BLKS) g_agg[tid] = 0ull;

    // ---- wait for gemv logits (acquire)
    if (tid == 0) {
        volatile unsigned* p = &g_gemvdone;
        while (*p < s_round2 * (unsigned)GEMV_BLKS) { }
    }
    __syncthreads();
    __threadfence();

    // ---- phase C: edgefill (dst/rank in registers; src coalesced)
#pragma unroll
    for (int it = 0; it < 4; it++) {
        int e0 = (gtid + it * gthreads) * 4;
        if (e0 >= N_EDGES) continue;
        if (e0 + 3 < N_EDGES) {
            int4 s4 = *(const int4*)(src + e0);
            int sv[4] = {s4.x, s4.y, s4.z, s4.w};
#pragma unroll
            for (int k = 0; k < 4; k++) {
                int d = ds[it * 4 + k];
                unsigned long long sd = g_sdoff[d];
                float ef = g_ssrc[sv[k]] + __uint_as_float((unsigned)sd);
                ef = (ef >= 0.0f) ? ef : NEG_SLOPE * ef;
                float ex = __expf(ef);
                int pos = (int)(sd >> 32) + rs[it * 4 + k];
                g_pack[pos] =
                    ((unsigned long long)__float_as_uint(ex) << 32) | (unsigned)sv[k];
            }
        } else {
#pragma unroll
            for (int k = 0; k < 4; k++) {
                int e = e0 + k;
                if (e >= N_EDGES) break;
                int s = src[e];
                int d = ds[it * 4 + k];
                unsigned long long sd = g_sdoff[d];
                float ef = g_ssrc[s] + __uint_as_float((unsigned)sd);
                ef = (ef >= 0.0f) ? ef : NEG_SLOPE * ef;
                float ex = __expf(ef);
                int pos = (int)(sd >> 32) + rs[it * 4 + k];
                g_pack[pos] =
                    ((unsigned long long)__float_as_uint(ex) << 32) | (unsigned)s;
            }
        }
    }
}

// ---------------- GEMM via mma.sync: z = h @ W (bf16 hi/lo, fp32 accum) ------
__global__ __launch_bounds__(256, 2) void gemm_mma_kernel(
        const float* __restrict__ h, const float* __restrict__ W) {
    extern __shared__ char smem[];
    const uint32_t smem_base = smem_to_u32(smem);
    const int tid  = threadIdx.x;
    const int wid  = tid >> 5;
    const int lane = tid & 31;
    const int row0 = blockIdx.x * 128;

    __nv_bfloat16* Bs_hi = (__nv_bfloat16*)(smem + SM_B_HI);
    __nv_bfloat16* Bs_lo = (__nv_bfloat16*)(smem + SM_B_LO);

    const int warpM = wid & 3;
    const int warpN = wid >> 2;
    const int rowBase = warpM * 32;
    const int nBase   = warpN * 64;

    float acc[2][8][4];
#pragma unroll
    for (int mt = 0; mt < 2; mt++)
#pragma unroll
        for (int nt = 0; nt < 8; nt++)
#pragma unroll
            for (int q = 0; q < 4; q++) acc[mt][nt][q] = 0.0f;

    const int m4 = lane >> 3;
    const int r8 = lane & 7;
    const uint32_t aoff = ((uint32_t)(rowBase + ((m4 & 1) << 3) + r8) * STRA +
                          (uint32_t)((m4 >> 1) << 3)) * 2;
    const uint32_t boff = ((uint32_t)(nBase + r8) * STRA +
                          (uint32_t)((m4 & 1) << 3)) * 2;
    const uint32_t aHiBase = smem_base + SM_A_HI + aoff;
    const uint32_t aLoBase = smem_base + SM_A_LO + aoff;
    const uint32_t bHiBase = smem_base + SM_B_HI + boff;
    const uint32_t bLoBase = smem_base + SM_B_LO + boff;

    for (int c = 0; c < 2; c++) {
        if (c) __syncthreads();
#pragma unroll
        for (int it = 0; it < 8; it++) {
            int flat = it * 256 + tid;
            int row  = flat >> 4;
            int k0   = (flat & 15) << 2;
            float4 v = make_float4(0.f, 0.f, 0.f, 0.f);
            if (row0 + row < N_NODES)
                v = ((const float4*)h)[(size_t)(row0 + row) * (DIM / 4) + (c * KC + k0) / 4];
            __nv_bfloat16 h0, h1, h2, h3, l0, l1, l2, l3;
            split_bf16(v.x, h0, l0); split_bf16(v.y, h1, l1);
            split_bf16(v.z, h2, l2); split_bf16(v.w, h3, l3);
            union { __nv_bfloat16 b[4]; unsigned long long u; } uh, ul;
            uh.b[0] = h0; uh.b[1] = h1; uh.b[2] = h2; uh.b[3] = h3;
            ul.b[0] = l0; ul.b[1] = l1; ul.b[2] = l2; ul.b[3] = l3;
            *(unsigned long long*)(smem + SM_A_HI + row * (STRA * 2) + k0 * 2) = uh.u;
            *(unsigned long long*)(smem + SM_A_LO + row * (STRA * 2) + k0 * 2) = ul.u;
        }
#pragma unroll
        for (int it = 0; it < 32; it++) {
            int flat = it * 256 + tid;
            int kk = flat >> 7;
            int n  = flat & 127;
            __nv_bfloat16 hi, lo;
            split_bf16(W[(c * KC + kk) * DIM + n], hi, lo);
            Bs_hi[n * STRA + kk] = hi;
            Bs_lo[n * STRA + kk] = lo;
        }
        __syncthreads();

#pragma unroll
        for (int ks = 0; ks < 4; ks++) {
            const uint32_t kb = (uint32_t)(ks * 16) * 2;
            uint32_t aHi[2][4], aLo[2][4], bHi[8][2], bLo[8][2];
#pragma unroll
            for (int mt = 0; mt < 2; mt++) {
                uint32_t ra = (uint32_t)(mt * 16 * STRA * 2) + kb;
                LDSM4(aHi[mt], aHiBase + ra);
                LDSM4(aLo[mt], aLoBase + ra);
            }
#pragma unroll
            for (int nt = 0; nt < 8; nt++) {
                uint32_t rb = (uint32_t)(nt * 8 * STRA * 2) + kb;
                LDSM2(bHi[nt], bHiBase + rb);
                LDSM2(bLo[nt], bLoBase + rb);
            }
#pragma unroll
            for (int mt = 0; mt < 2; mt++)
#pragma unroll
                for (int nt = 0; nt < 8; nt++) {
                    MMA_BF16(acc[mt][nt], aHi[mt], bHi[nt]);
                    MMA_BF16(acc[mt][nt], aHi[mt], bLo[nt]);
                    MMA_BF16(acc[mt][nt], aLo[mt], bHi[nt]);
                }
        }
    }

    const int g  = lane >> 2;
    const int tg = lane & 3;
#pragma unroll
    for (int mt = 0; mt < 2; mt++) {
        int rowA = row0 + rowBase + mt * 16 + g;
        int rowB = rowA + 8;
#pragma unroll
        for (int nt = 0; nt < 8; nt++) {
            int col = nBase + nt * 8 + tg * 2;
            if (rowA < N_NODES)
                *(__half2*)&g_zh[(size_t)rowA * DIM + col] =
                    __floats2half2_rn(acc[mt][nt][0], acc[mt][nt][1]);
            if (rowB < N_NODES)
                *(__half2*)&g_zh[(size_t)rowB * DIM + col] =
                    __floats2half2_rn(acc[mt][nt][2], acc[mt][nt][3]);
        }
    }
}

// ---------------- gather v2: 2 edges x 16 lanes, one warp per node ------------
__global__ __launch_bounds__(256) void gather_kernel(float* __restrict__ out) {
    int node = (blockIdx.x * blockDim.x + threadIdx.x) >> 5;
    int lane = threadIdx.x & 31;
    if (node >= N_NODES) return;
    int start = g_offs[node];
    int end   = g_offs[node + 1];
    const int eg = lane >> 4;
    const int sl = lane & 15;

    float acc[8];
#pragma unroll
    for (int k = 0; k < 8; k++) acc[k] = 0.0f;
    float sumex = 0.0f;

    for (int base = start; base < end; base += 32) {
        int idx = base + lane;
        unsigned long long pk = (idx < end) ? g_pack[idx] : 0ull;  // exp=0 pad
        int   s_l  = (int)(unsigned)(pk & 0xffffffffull);
        float ex_l = __uint_as_float((unsigned)(pk >> 32));
        sumex += ex_l;
        int cnt = min(32, end - base);
        int pairs = (cnt + 1) >> 1;
#pragma unroll 4
        for (int p = 0; p < pairs; p++) {
            int j = p * 2 + eg;
            int   ss = __shfl_sync(0xffffffffu, s_l, j);
            float a  = __shfl_sync(0xffffffffu, ex_l, j);
            uint4 raw = ((const uint4*)g_zh)[(size_t)ss * 16 + sl];
            __half2* hp = (__half2*)&raw;
            float2 f0 = __half22float2(hp[0]);
            float2 f1 = __half22float2(hp[1]);
            float2 f2 = __half22float2(hp[2]);
            float2 f3 = __half22float2(hp[3]);
            acc[0] = fmaf(a, f0.x, acc[0]);
            acc[1] = fmaf(a, f0.y, acc[1]);
            acc[2] = fmaf(a, f1.x, acc[2]);
            acc[3] = fmaf(a, f1.y, acc[3]);
            acc[4] = fmaf(a, f2.x, acc[4]);
            acc[5] = fmaf(a, f2.y, acc[5]);
            acc[6] = fmaf(a, f3.x, acc[6]);
            acc[7] = fmaf(a, f3.y, acc[7]);
        }
    }
#pragma unroll
    for (int k = 0; k < 8; k++)
        acc[k] += __shfl_xor_sync(0xffffffffu, acc[k], 16);
#pragma unroll
    for (int o = 16; o > 0; o >>= 1)
        sumex += __shfl_xor_sync(0xffffffffu, sumex, o);

    if (lane < 16) {
        float4 v0, v1;
        if (end > start) {
            float inv = 1.0f / sumex;
            v0 = make_float4(acc[0] * inv, acc[1] * inv, acc[2] * inv, acc[3] * inv);
            v1 = make_float4(acc[4] * inv, acc[5] * inv, acc[6] * inv, acc[7] * inv);
        } else {
            v0 = make_float4(0.f, 0.f, 0.f, 0.f);
            v1 = v0;
        }
        float* p = out + (size_t)node * DIM + sl * 8;
        *(float4*)p       = v0;
        *(float4*)(p + 4) = v1;
    }
}

// ---------------- launch: gemv(s3) | histscan+fill(s2) | gemm(main) -> gather --
// All forked streams are re-joined to stream 0 before the final kernel
// (graph capture requires every branch joined; device-side counters handle
// the actual fine-grained ordering).
extern "C" void kernel_launch(void* const* d_in, const int* in_sizes, int n_in,
                              void* d_out, int out_size) {
    const float* h     = (const float*)d_in[0];
    const int*   src   = (const int*)d_in[1];
    const int*   dst   = (const int*)d_in[2];
    const float* W     = (const float*)d_in[3];
    const float* a_src = (const float*)d_in[4];
    const float* a_dst = (const float*)d_in[5];
    float* out = (float*)d_out;

    static cudaStream_t s2 = nullptr, s3 = nullptr;
    static cudaEvent_t evFork = nullptr, evS3 = nullptr, evJoin = nullptr;
    if (!s2) {
        cudaFuncSetAttribute(gemm_mma_kernel,
                             cudaFuncAttributeMaxDynamicSharedMemorySize, SM_TOTAL);
        cudaStreamCreateWithFlags(&s2, cudaStreamNonBlocking);
        cudaStreamCreateWithFlags(&s3, cudaStreamNonBlocking);
        cudaEventCreateWithFlags(&evFork, cudaEventDisableTiming);
        cudaEventCreateWithFlags(&evS3, cudaEventDisableTiming);
        cudaEventCreateWithFlags(&evJoin, cudaEventDisableTiming);
    }

    cudaEventRecord(evFork, 0);
    cudaStreamWaitEvent(s2, evFork, 0);
    cudaStreamWaitEvent(s3, evFork, 0);

    // s3: logits (fused gemv) — launched before histscan so a serialized
    // execution still satisfies phase C's counter spin.
    gemv_kernel<<<GEMV_BLKS, 256, 0, s3>>>(h, W, a_src, a_dst);
    cudaEventRecord(evS3, s3);          // join s3 into the graph

    // s2: hist + scan + edgefill, one kernel (waits on gemv via counter)
    histscan_kernel<<<N_SCAN_BLKS, SCAN_BLK, 0, s2>>>(src, dst);
    cudaEventRecord(evJoin, s2);

    // main: GEMM (z only, bf16 3-pass)
    gemm_mma_kernel<<<(N_NODES + 127) / 128, 256, SM_TOTAL>>>(h, W);

    // join ALL branches before the final kernel (capture-legal graph)
    cudaStreamWaitEvent(0, evJoin, 0);
    cudaStreamWaitEvent(0, evS3, 0);
    gather_kernel<<<(N_NODES * 32 + 255) / 256, 256>>>(out);
}

// round 17
// speedup vs baseline: 1.4568x; 1.4568x over previous
#include <cuda_runtime.h>
#include <cuda_bf16.h>
#include <cuda_fp16.h>
#include <cstdint>

#define N_NODES 50000
#define N_EDGES 800000
#define DIM 128
#define NEG_SLOPE 0.01f

#define SCAN_BLK 1024
#define N_SCAN_BLKS ((N_NODES + SCAN_BLK - 1) / SCAN_BLK)   // 49

// ---------------- scratch (static device globals; zero-init at load) --------
__device__ __half             g_zh[(size_t)N_NODES * DIM];  // z = h @ W (fp16)
__device__ float              g_ssrc[N_NODES];              // h . (W a_src)
__device__ unsigned long long g_sdoff[N_NODES];             // {offs(hi) | sdst bits(lo)}
__device__ float              g_wa[2 * DIM];                // W@a_src | W@a_dst
__device__ int                g_count[N_NODES];             // in-degree histogram
__device__ int                g_offs[N_NODES + 1];          // CSR offsets (gather)
__device__ int                g_rank[N_EDGES];              // edge rank within dst
__device__ unsigned long long g_agg[N_SCAN_BLKS];           // scan aggregates
__device__ unsigned long long g_pack[N_EDGES];              // {exp(e), src} by dst

// ======================= mma.sync helpers (plain sm_103 OK) ==================
__device__ __forceinline__ uint32_t smem_to_u32(const void* p) {
    uint32_t a;
    asm("{ .reg .u64 t; cvta.to.shared.u64 t, %1; cvt.u32.u64 %0, t; }"
        : "=r"(a) : "l"(p));
    return a;
}
#define LDSM4(r, addr) \
    asm volatile("ldmatrix.sync.aligned.m8n8.x4.shared.b16 {%0,%1,%2,%3}, [%4];" \
        : "=r"((r)[0]), "=r"((r)[1]), "=r"((r)[2]), "=r"((r)[3]) : "r"(addr))
#define LDSM2(r, addr) \
    asm volatile("ldmatrix.sync.aligned.m8n8.x2.shared.b16 {%0,%1}, [%2];" \
        : "=r"((r)[0]), "=r"((r)[1]) : "r"(addr))
#define MMA_BF16(c, a, b) \
    asm volatile("mma.sync.aligned.m16n8k16.row.col.f32.bf16.bf16.f32 " \
        "{%0,%1,%2,%3}, {%4,%5,%6,%7}, {%8,%9}, {%0,%1,%2,%3};" \
        : "+f"((c)[0]), "+f"((c)[1]), "+f"((c)[2]), "+f"((c)[3]) \
        : "r"((a)[0]), "r"((a)[1]), "r"((a)[2]), "r"((a)[3]), "r"((b)[0]), "r"((b)[1]))

#define STRA 72    // bf16 elems per smem row (64 data + 8 pad) -> conflict-free
#define KC   64    // K-chunk

// dynamic smem layout (bytes)
#define SM_A_HI  0
#define SM_A_LO  (SM_A_HI + 128 * STRA * 2)
#define SM_B_HI  (SM_A_LO + 128 * STRA * 2)
#define SM_B_LO  (SM_B_HI + 128 * STRA * 2)
#define SM_TOTAL (SM_B_LO + 128 * STRA * 2)   // 73728 -> 2 CTAs/SM

__device__ __forceinline__ void split_bf16(float x, __nv_bfloat16& hi, __nv_bfloat16& lo) {
    hi = __float2bfloat16(x);
    lo = __float2bfloat16(x - __bfloat162float(hi));
}

// ---------------- histogram of dst; atomic return value = edge rank ----------
__global__ void hist_kernel(const int* __restrict__ dst) {
    int i = blockIdx.x * blockDim.x + threadIdx.x;
    int e0 = i * 4;
    if (e0 + 3 < N_EDGES) {
        int4 d = *(const int4*)(dst + e0);
        int4 r;
        r.x = atomicAdd(&g_count[d.x], 1);
        r.y = atomicAdd(&g_count[d.y], 1);
        r.z = atomicAdd(&g_count[d.z], 1);
        r.w = atomicAdd(&g_count[d.w], 1);
        *(int4*)(g_rank + e0) = r;
    } else {
        for (int e = e0; e < N_EDGES; e++)
            g_rank[e] = atomicAdd(&g_count[dst[e]], 1);
    }
}

// ---------------- gemv stage 1: wa_src = W @ a_src, wa_dst = W @ a_dst --------
__global__ void gemv_wa_kernel(const float* __restrict__ W,
                               const float* __restrict__ a_src,
                               const float* __restrict__ a_dst) {
    int warp = threadIdx.x >> 5, lane = threadIdx.x & 31;
    float4 as = ((const float4*)a_src)[lane];
    float4 ad = ((const float4*)a_dst)[lane];
#pragma unroll
    for (int it = 0; it < 16; it++) {
        int k = warp + it * 8;
        float4 w = ((const float4*)W)[k * 32 + lane];
        float ps = w.x * as.x + w.y * as.y + w.z * as.z + w.w * as.w;
        float pd = w.x * ad.x + w.y * ad.y + w.z * ad.z + w.w * ad.w;
#pragma unroll
        for (int o = 16; o > 0; o >>= 1) {
            ps += __shfl_xor_sync(0xffffffffu, ps, o);
            pd += __shfl_xor_sync(0xffffffffu, pd, o);
        }
        if (lane == 0) { g_wa[k] = ps; g_wa[DIM + k] = pd; }
    }
}

// ---------------- gemv stage 2: ssrc[i] = h[i].wa_src, sdst -> sdoff.lo -------
__global__ __launch_bounds__(256) void gemv_rows_kernel(const float* __restrict__ h) {
    int row  = (blockIdx.x * blockDim.x + threadIdx.x) >> 5;
    int lane = threadIdx.x & 31;
    if (row >= N_NODES) return;
    float4 v  = ((const float4*)h)[(size_t)row * 32 + lane];
    float4 ws = ((const float4*)g_wa)[lane];
    float4 wd = ((const float4*)g_wa)[32 + lane];
    float ps = v.x * ws.x + v.y * ws.y + v.z * ws.z + v.w * ws.w;
    float pd = v.x * wd.x + v.y * wd.y + v.z * wd.z + v.w * wd.w;
#pragma unroll
    for (int o = 16; o > 0; o >>= 1) {
        ps += __shfl_xor_sync(0xffffffffu, ps, o);
        pd += __shfl_xor_sync(0xffffffffu, pd, o);
    }
    if (lane == 0) {
        g_ssrc[row] = ps;
        ((unsigned*)&g_sdoff[row])[0] = __float_as_uint(pd);
    }
}

// ---------------- GEMM via mma.sync: z = h @ W (bf16 hi/lo, fp32 accum) ------
__global__ __launch_bounds__(256, 2) void gemm_mma_kernel(
        const float* __restrict__ h, const float* __restrict__ W) {
    extern __shared__ char smem[];
    const uint32_t smem_base = smem_to_u32(smem);
    const int tid  = threadIdx.x;
    const int wid  = tid >> 5;
    const int lane = tid & 31;
    const int row0 = blockIdx.x * 128;

    __nv_bfloat16* Bs_hi = (__nv_bfloat16*)(smem + SM_B_HI);
    __nv_bfloat16* Bs_lo = (__nv_bfloat16*)(smem + SM_B_LO);

    const int warpM = wid & 3;
    const int warpN = wid >> 2;
    const int rowBase = warpM * 32;
    const int nBase   = warpN * 64;

    float acc[2][8][4];
#pragma unroll
    for (int mt = 0; mt < 2; mt++)
#pragma unroll
        for (int nt = 0; nt < 8; nt++)
#pragma unroll
            for (int q = 0; q < 4; q++) acc[mt][nt][q] = 0.0f;

    const int m4 = lane >> 3;
    const int r8 = lane & 7;
    const uint32_t aoff = ((uint32_t)(rowBase + ((m4 & 1) << 3) + r8) * STRA +
                          (uint32_t)((m4 >> 1) << 3)) * 2;
    const uint32_t boff = ((uint32_t)(nBase + r8) * STRA +
                          (uint32_t)((m4 & 1) << 3)) * 2;
    const uint32_t aHiBase = smem_base + SM_A_HI + aoff;
    const uint32_t aLoBase = smem_base + SM_A_LO + aoff;
    const uint32_t bHiBase = smem_base + SM_B_HI + boff;
    const uint32_t bLoBase = smem_base + SM_B_LO + boff;

    for (int c = 0; c < 2; c++) {
        if (c) __syncthreads();
#pragma unroll
        for (int it = 0; it < 8; it++) {
            int flat = it * 256 + tid;
            int row  = flat >> 4;
            int k0   = (flat & 15) << 2;
            float4 v = make_float4(0.f, 0.f, 0.f, 0.f);
            if (row0 + row < N_NODES)
                v = ((const float4*)h)[(size_t)(row0 + row) * (DIM / 4) + (c * KC + k0) / 4];
            __nv_bfloat16 h0, h1, h2, h3, l0, l1, l2, l3;
            split_bf16(v.x, h0, l0); split_bf16(v.y, h1, l1);
            split_bf16(v.z, h2, l2); split_bf16(v.w, h3, l3);
            union { __nv_bfloat16 b[4]; unsigned long long u; } uh, ul;
            uh.b[0] = h0; uh.b[1] = h1; uh.b[2] = h2; uh.b[3] = h3;
            ul.b[0] = l0; ul.b[1] = l1; ul.b[2] = l2; ul.b[3] = l3;
            *(unsigned long long*)(smem + SM_A_HI + row * (STRA * 2) + k0 * 2) = uh.u;
            *(unsigned long long*)(smem + SM_A_LO + row * (STRA * 2) + k0 * 2) = ul.u;
        }
#pragma unroll
        for (int it = 0; it < 32; it++) {
            int flat = it * 256 + tid;
            int kk = flat >> 7;
            int n  = flat & 127;
            __nv_bfloat16 hi, lo;
            split_bf16(W[(c * KC + kk) * DIM + n], hi, lo);
            Bs_hi[n * STRA + kk] = hi;
            Bs_lo[n * STRA + kk] = lo;
        }
        __syncthreads();

#pragma unroll
        for (int ks = 0; ks < 4; ks++) {
            const uint32_t kb = (uint32_t)(ks * 16) * 2;
            uint32_t aHi[2][4], aLo[2][4], bHi[8][2], bLo[8][2];
#pragma unroll
            for (int mt = 0; mt < 2; mt++) {
                uint32_t ra = (uint32_t)(mt * 16 * STRA * 2) + kb;
                LDSM4(aHi[mt], aHiBase + ra);
                LDSM4(aLo[mt], aLoBase + ra);
            }
#pragma unroll
            for (int nt = 0; nt < 8; nt++) {
                uint32_t rb = (uint32_t)(nt * 8 * STRA * 2) + kb;
                LDSM2(bHi[nt], bHiBase + rb);
                LDSM2(bLo[nt], bLoBase + rb);
            }
#pragma unroll
            for (int mt = 0; mt < 2; mt++)
#pragma unroll
                for (int nt = 0; nt < 8; nt++) {
                    MMA_BF16(acc[mt][nt], aHi[mt], bHi[nt]);
                    MMA_BF16(acc[mt][nt], aHi[mt], bLo[nt]);
                    MMA_BF16(acc[mt][nt], aLo[mt], bHi[nt]);
                }
        }
    }

    const int g  = lane >> 2;
    const int tg = lane & 3;
#pragma unroll
    for (int mt = 0; mt < 2; mt++) {
        int rowA = row0 + rowBase + mt * 16 + g;
        int rowB = rowA + 8;
#pragma unroll
        for (int nt = 0; nt < 8; nt++) {
            int col = nBase + nt * 8 + tg * 2;
            if (rowA < N_NODES)
                *(__half2*)&g_zh[(size_t)rowA * DIM + col] =
                    __floats2half2_rn(acc[mt][nt][0], acc[mt][nt][1]);
            if (rowB < N_NODES)
                *(__half2*)&g_zh[(size_t)rowB * DIM + col] =
                    __floats2half2_rn(acc[mt][nt][2], acc[mt][nt][3]);
        }
    }
}

// ---------------- scan: single kernel, parallel lookback, self-cleaning ------
__global__ __launch_bounds__(SCAN_BLK) void scan_kernel() {
    __shared__ int wt[32];
    __shared__ int s_vals[64];
    __shared__ int s_base;
    const int tid = threadIdx.x, lane = tid & 31, warp = tid >> 5;
    const int bid = blockIdx.x;
    const int i = bid * SCAN_BLK + tid;

    int v = 0;
    if (i < N_NODES) { v = g_count[i]; g_count[i] = 0; }
    int incl = v;
#pragma unroll
    for (int o = 1; o < 32; o <<= 1) {
        int t = __shfl_up_sync(0xffffffffu, incl, o);
        if (lane >= o) incl += t;
    }
    if (lane == 31) wt[warp] = incl;
    __syncthreads();
    if (warp == 0) {
        int x = wt[lane], ix = x;
#pragma unroll
        for (int o = 1; o < 32; o <<= 1) {
            int t = __shfl_up_sync(0xffffffffu, ix, o);
            if (lane >= o) ix += t;
        }
        wt[lane] = ix - x;
        if (lane == 31)
            atomicExch(&g_agg[bid], (1ull << 32) | (unsigned)ix);
    }
    __syncthreads();
    if (tid < bid) {
        volatile unsigned long long* p = (volatile unsigned long long*)&g_agg[tid];
        unsigned long long x;
        do { x = *p; } while (!(x >> 32));
        s_vals[tid] = (int)(unsigned)x;
    }
    __syncthreads();
    if (tid == 0) {
        int b = 0;
        for (int j = 0; j < bid; j++) b += s_vals[j];
        s_base = b;
        if (bid == N_SCAN_BLKS - 1) g_offs[N_NODES] = N_EDGES;
    }
    __syncthreads();
    if (i < N_NODES) {
        int off = s_base + wt[warp] + incl - v;
        g_offs[i] = off;
        ((int*)&g_sdoff[i])[1] = off;
    }
}

// ---------------- edgefill: 2 edges/thread, no atomics ------------------------
// No max-shift: |e| statistically bounded (~15), exp fits fp32, softmax invariant.
__global__ void edgefill_kernel(const int* __restrict__ src, const int* __restrict__ dst) {
    int t = blockIdx.x * blockDim.x + threadIdx.x;
    if (t < N_SCAN_BLKS) g_agg[t] = 0ull;   // clean for next replay
    int e0 = t * 2;
    if (e0 + 1 < N_EDGES) {
        int2 s2 = *(const int2*)(src + e0);
        int2 d2 = *(const int2*)(dst + e0);
        int2 r2 = *(const int2*)(g_rank + e0);
        unsigned long long sd0 = g_sdoff[d2.x];
        unsigned long long sd1 = g_sdoff[d2.y];
        float ss0 = g_ssrc[s2.x];
        float ss1 = g_ssrc[s2.y];
        float f0 = ss0 + __uint_as_float((unsigned)sd0);
        float f1 = ss1 + __uint_as_float((unsigned)sd1);
        f0 = (f0 >= 0.f) ? f0 : NEG_SLOPE * f0;
        f1 = (f1 >= 0.f) ? f1 : NEG_SLOPE * f1;
        g_pack[(int)(sd0 >> 32) + r2.x] =
            ((unsigned long long)__float_as_uint(__expf(f0)) << 32) | (unsigned)s2.x;
        g_pack[(int)(sd1 >> 32) + r2.y] =
            ((unsigned long long)__float_as_uint(__expf(f1)) << 32) | (unsigned)s2.y;
    } else {
        for (int e = e0; e < N_EDGES; e++) {
            int s = src[e], d = dst[e];
            unsigned long long sd = g_sdoff[d];
            float ef = g_ssrc[s] + __uint_as_float((unsigned)sd);
            ef = (ef >= 0.0f) ? ef : NEG_SLOPE * ef;
            float ex = __expf(ef);
            int pos = (int)(sd >> 32) + g_rank[e];
            g_pack[pos] = ((unsigned long long)__float_as_uint(ex) << 32) | (unsigned)s;
        }
    }
}

// ---------------- gather v2: 2 edges x 16 lanes, one warp per node ------------
__global__ __launch_bounds__(256) void gather_kernel(float* __restrict__ out) {
    int node = (blockIdx.x * blockDim.x + threadIdx.x) >> 5;
    int lane = threadIdx.x & 31;
    if (node >= N_NODES) return;
    int start = g_offs[node];
    int end   = g_offs[node + 1];
    const int eg = lane >> 4;
    const int sl = lane & 15;

    float acc[8];
#pragma unroll
    for (int k = 0; k < 8; k++) acc[k] = 0.0f;
    float sumex = 0.0f;

    for (int base = start; base < end; base += 32) {
        int idx = base + lane;
        unsigned long long pk = (idx < end) ? g_pack[idx] : 0ull;  // exp=0 pad
        int   s_l  = (int)(unsigned)(pk & 0xffffffffull);
        float ex_l = __uint_as_float((unsigned)(pk >> 32));
        sumex += ex_l;
        int cnt = min(32, end - base);
        int pairs = (cnt + 1) >> 1;
#pragma unroll 4
        for (int p = 0; p < pairs; p++) {
            int j = p * 2 + eg;
            int   ss = __shfl_sync(0xffffffffu, s_l, j);
            float a  = __shfl_sync(0xffffffffu, ex_l, j);
            uint4 raw = ((const uint4*)g_zh)[(size_t)ss * 16 + sl];
            __half2* hp = (__half2*)&raw;
            float2 f0 = __half22float2(hp[0]);
            float2 f1 = __half22float2(hp[1]);
            float2 f2 = __half22float2(hp[2]);
            float2 f3 = __half22float2(hp[3]);
            acc[0] = fmaf(a, f0.x, acc[0]);
            acc[1] = fmaf(a, f0.y, acc[1]);
            acc[2] = fmaf(a, f1.x, acc[2]);
            acc[3] = fmaf(a, f1.y, acc[3]);
            acc[4] = fmaf(a, f2.x, acc[4]);
            acc[5] = fmaf(a, f2.y, acc[5]);
            acc[6] = fmaf(a, f3.x, acc[6]);
            acc[7] = fmaf(a, f3.y, acc[7]);
        }
    }
#pragma unroll
    for (int k = 0; k < 8; k++)
        acc[k] += __shfl_xor_sync(0xffffffffu, acc[k], 16);
#pragma unroll
    for (int o = 16; o > 0; o >>= 1)
        sumex += __shfl_xor_sync(0xffffffffu, sumex, o);

    if (lane < 16) {
        float4 v0, v1;
        if (end > start) {
            float inv = 1.0f / sumex;
            v0 = make_float4(acc[0] * inv, acc[1] * inv, acc[2] * inv, acc[3] * inv);
            v1 = make_float4(acc[4] * inv, acc[5] * inv, acc[6] * inv, acc[7] * inv);
        } else {
            v0 = make_float4(0.f, 0.f, 0.f, 0.f);
            v1 = v0;
        }
        float* p = out + (size_t)node * DIM + sl * 8;
        *(float4*)p       = v0;
        *(float4*)(p + 4) = v1;
    }
}

// ---------------- launch: 3-way fork, join before gather ------------------------
extern "C" void kernel_launch(void* const* d_in, const int* in_sizes, int n_in,
                              void* d_out, int out_size) {
    const float* h     = (const float*)d_in[0];
    const int*   src   = (const int*)d_in[1];
    const int*   dst   = (const int*)d_in[2];
    const float* W     = (const float*)d_in[3];
    const float* a_src = (const float*)d_in[4];
    const float* a_dst = (const float*)d_in[5];
    float* out = (float*)d_out;

    static cudaStream_t s2 = nullptr, s3 = nullptr;
    static cudaEvent_t evFork = nullptr, evS3 = nullptr, evJoin = nullptr;
    if (!s2) {
        cudaFuncSetAttribute(gemm_mma_kernel,
                             cudaFuncAttributeMaxDynamicSharedMemorySize, SM_TOTAL);
        cudaStreamCreateWithFlags(&s2, cudaStreamNonBlocking);
        cudaStreamCreateWithFlags(&s3, cudaStreamNonBlocking);
        cudaEventCreateWithFlags(&evFork, cudaEventDisableTiming);
        cudaEventCreateWithFlags(&evS3, cudaEventDisableTiming);
        cudaEventCreateWithFlags(&evJoin, cudaEventDisableTiming);
    }

    cudaEventRecord(evFork, 0);
    cudaStreamWaitEvent(s2, evFork, 0);
    cudaStreamWaitEvent(s3, evFork, 0);

    // s3: logits via associativity — h @ (W @ a)
    gemv_wa_kernel<<<1, 256, 0, s3>>>(W, a_src, a_dst);
    gemv_rows_kernel<<<(N_NODES * 32 + 255) / 256, 256, 0, s3>>>(h);
    cudaEventRecord(evS3, s3);

    // s2: CSR build, then edgefill once logits are ready
    hist_kernel<<<(N_EDGES / 4 + 255) / 256, 256, 0, s2>>>(dst);
    scan_kernel<<<N_SCAN_BLKS, SCAN_BLK, 0, s2>>>();
    cudaStreamWaitEvent(s2, evS3, 0);
    edgefill_kernel<<<(N_EDGES / 2 + 255) / 256, 256, 0, s2>>>(src, dst);
    cudaEventRecord(evJoin, s2);

    // main: GEMM (z only)
    gemm_mma_kernel<<<(N_NODES + 127) / 128, 256, SM_TOTAL>>>(h, W);

    // join: gather needs z + pack + offs
    cudaStreamWaitEvent(0, evJoin, 0);
    gather_kernel<<<(N_NODES * 32 + 255) / 256, 256>>>(out);
}